// round 12
// baseline (speedup 1.0000x reference)
#include <cuda_runtime.h>
#include <cstdint>

// Problem constants (fixed by reference setup_inputs)
#define BB   16
#define NN   1000
#define KK   50
#define DD   128
#define NTHREADS 256
#define WPB  8            // warps (= nodes) per block
#define CAND_CAP 96       // per-warp candidate buffer (expected ~52-56)

// Output layout (float32, concatenation of reference outputs):
//   [0,        2048000)   x = init_embeddings
//   [2048000,  2848000)   edge_index row 0 (src)
//   [2848000,  3648000)   edge_index row 1 (dst)
//   [3648000, 106048000)  edge_emb [B*n*k, D]
#define X_ELEMS   (BB * NN * DD)
#define E_ELEMS   (BB * NN * KK)

#define FULLMASK 0xFFFFFFFFu
#define BIN_SCALE 2048.0f   // d^2 in [0, 0.125) -> bins 0..255; rest clamps to 255

__global__ __launch_bounds__(NTHREADS, 7)
void tsp_topk_kernel(const float* __restrict__ locs,   // [B, N, 2]
                     const float* __restrict__ xin,    // [B, N, 128]
                     const float* __restrict__ W,      // [128]
                     const float* __restrict__ bias,   // [128]
                     float* __restrict__ out)
{
    __shared__ __align__(16) float2 sloc[1024];            // 8192 B (pads = huge)
    __shared__ unsigned int hist[WPB][256];                // 8 KB (per-warp)
    __shared__ unsigned long long cand[WPB][CAND_CAP];     // 6 KB (per-warp)
    __shared__ float        sdist[WPB][KK];                // 1.6 KB
    __shared__ unsigned int snbr [WPB][KK];                // 1.6 KB

    const int tid  = threadIdx.x;
    const int lane = tid & 31;
    const int wid  = tid >> 5;
    const int b    = blockIdx.x / (NN / WPB);   // 125 blocks per batch, exact
    const int node = blockIdx.x * WPB + wid;    // global node index b*NN + i
    const int i    = node - b * NN;

    // x output first: keeps DRAM busy during the selection phase.
    reinterpret_cast<float4*>(out)[(size_t)node * 32 + lane] =
        reinterpret_cast<const float4*>(xin)[(size_t)node * 32 + lane];

    // Stage this batch's locations (float4 = 2 points/load); pad slots
    // 1000..1023 get huge coords (bin clamps to 255, never selected). The
    // only block-wide barrier in the kernel.
    {
        const float4* l4 = reinterpret_cast<const float4*>(locs + (size_t)b * NN * 2);
        float4*       s4 = reinterpret_cast<float4*>(sloc);
        const float4  big = make_float4(2e9f, 2e9f, 2e9f, 2e9f);
        for (int t = tid; t < 512; t += NTHREADS)
            s4[t] = (t < 500) ? l4[t] : big;
    }
    #pragma unroll
    for (int j = 0; j < 8; ++j) hist[wid][lane * 8 + j] = 0;
    __syncthreads();

    const float2 my = sloc[i];
    const float4* s4loc = reinterpret_cast<const float4*>(sloc);

    // Exact jax-f32 d^2 (no fma contraction) and its monotone linear bin:
    // d2a < d2b => bin(a) <= bin(b); equal d^2 => equal bin. Self point
    // (d^2 = 1e-12 -> bin 0) is included predicate-free and compensated by
    // targeting rank KK+1 in the cutoff; pads clamp to bin 255. CVT float->
    // int saturates per PTX, so huge pad values are safe.
    #define D2ANDBIN(px, py, d2, bin)                                         \
        do {                                                                  \
            float dx = my.x - (px);                                           \
            float dy = my.y - (py);                                           \
            (d2) = __fadd_rn(__fadd_rn(__fmul_rn(dx, dx),                     \
                                       __fmul_rn(dy, dy)), 1e-12f);           \
            (bin) = min(255, (int)((d2) * BIN_SCALE));                        \
        } while (0)

    // ---- Pass 1: single-level histogram on the fixed 256-bin d^2 scale.
    // match_any aggregation: the many far points collapse into bin 255 and
    // cost one atomic per warp-iteration. ----
    #pragma unroll 4
    for (int j = 0; j < 16; ++j) {
        const float4 p = s4loc[lane + 32 * j];
        float d2a, d2b; int ba, bb;
        D2ANDBIN(p.x, p.y, d2a, ba);
        D2ANDBIN(p.z, p.w, d2b, bb);
        unsigned int m0 = __match_any_sync(FULLMASK, ba);
        if (lane == __ffs(m0) - 1) atomicAdd(&hist[wid][ba], __popc(m0));
        unsigned int m1 = __match_any_sync(FULLMASK, bb);
        if (lane == __ffs(m1) - 1) atomicAdd(&hist[wid][bb], __popc(m1));
    }
    __syncwarp();

    // ---- Cutoff: bin c of the (KK+1)-th smallest value INCLUDING self
    // (self is the global minimum, so rank KK+1 of all == rank KK of real
    // neighbors). Compaction threshold = c + 1: the extra bin spans 4.9e-4
    // in d^2, far wider than the ~1e-9 window of any sqrt-rounding tie at
    // the rank-50 boundary, so every potential tie is captured. ----
    int cstop;
    {
        const unsigned int KT = KK + 1;
        unsigned int h[8], s = 0;
        #pragma unroll
        for (int j = 0; j < 8; ++j) { h[j] = hist[wid][lane * 8 + j]; s += h[j]; }
        unsigned int incl = s;
        #pragma unroll
        for (int o = 1; o < 32; o <<= 1) {
            unsigned int x = __shfl_up_sync(FULLMASK, incl, o);
            if (lane >= o) incl += x;
        }
        const unsigned int e   = incl - s;
        const bool         has = (e < KT && KT <= incl);   // exactly one lane
        int cc = 0;
        if (has) {
            unsigned int cum = e;
            #pragma unroll
            for (int j = 0; j < 8; ++j) {
                if (KT <= cum + h[j]) { cc = lane * 8 + j; break; }
                cum += h[j];
            }
        }
        const int srcl = __ffs(__ballot_sync(FULLMASK, has)) - 1;
        cstop = __shfl_sync(FULLMASK, cc, srcl) + 1;
    }

    // ---- Pass 2: compact all items with bin <= cstop (excluding self) and
    // immediately rewrite as the exact jax ordering key (bits(rn_sqrt(d^2))
    // << 10) | idx — ties break to the lower index like lax.top_k. Register
    // running-prefix, no atomics, no further passes. ----
    unsigned int cnt = 0;
    #pragma unroll 4
    for (int j = 0; j < 16; ++j) {
        const int    q  = lane + 32 * j;
        const float4 p  = s4loc[q];
        const int    t0 = 2 * q;
        float d2a, d2b; int ba, bb;
        D2ANDBIN(p.x, p.y, d2a, ba);
        D2ANDBIN(p.z, p.w, d2b, bb);

        bool         sel = (ba <= cstop) && (t0 != i);
        unsigned int msk = __ballot_sync(FULLMASK, sel);
        if (sel) {
            unsigned int pos = cnt + __popc(msk & ((1u << lane) - 1u));
            if (pos < CAND_CAP) {
                float d = __fsqrt_rn(d2a);                 // IEEE rn sqrt
                cand[wid][pos] =
                    ((unsigned long long)__float_as_uint(d) << 10) | (unsigned)t0;
            }
        }
        cnt += __popc(msk);

        sel = (bb <= cstop) && ((t0 + 1) != i);
        msk = __ballot_sync(FULLMASK, sel);
        if (sel) {
            unsigned int pos = cnt + __popc(msk & ((1u << lane) - 1u));
            if (pos < CAND_CAP) {
                float d = __fsqrt_rn(d2b);
                cand[wid][pos] =
                    ((unsigned long long)__float_as_uint(d) << 10)
                    | (unsigned)(t0 + 1);
            }
        }
        cnt += __popc(msk);
    }
    const unsigned int m = min(cnt, (unsigned)CAND_CAP);
    __syncwarp();

    // ---- Rank-select: keys unique (idx in low bits) -> ranks are a
    // permutation; broadcast-LDS counting loop, no sort, no barriers. ----
    for (unsigned int q = lane; q < m; q += 32) {
        const unsigned long long mykey = cand[wid][q];
        unsigned int rk = 0;
        #pragma unroll 4
        for (unsigned int t = 0; t < m; ++t)
            rk += (cand[wid][t] < mykey);
        if (rk < KK) {
            sdist[wid][rk] = __uint_as_float((unsigned int)(mykey >> 10));
            snbr [wid][rk] = (unsigned int)(mykey & 1023u);
        }
    }
    __syncwarp();

    // W/bias loads issued before the edge_index stores so their L2 latency
    // hides under those stores.
    const float4 w4 = __ldg(reinterpret_cast<const float4*>(W) + lane);
    const float4 b4 = __ldg(reinterpret_cast<const float4*>(bias) + lane);

    // ---- edge_index (coalesced, as float). ----
    {
        float* srcp = out + X_ELEMS;
        float* dstp = srcp + E_ELEMS;
        const long long e0 = (long long)node * KK;
        #pragma unroll
        for (int s = lane; s < KK; s += 32) {
            srcp[e0 + s] = (float)node;
            dstp[e0 + s] = (float)(b * NN + (int)snbr[wid][s]);
        }
    }

    // ---- edge_emb[e, :] = dist_e * W + bias; 50 streaming STG.128 rows. ----
    float4* emb = reinterpret_cast<float4*>(out + X_ELEMS + 2LL * E_ELEMS);
    const long long base = (long long)node * KK;
    #pragma unroll 10
    for (int s = 0; s < KK; ++s) {
        const float dd = sdist[wid][s];
        float4 v;
        v.x = fmaf(dd, w4.x, b4.x);
        v.y = fmaf(dd, w4.y, b4.y);
        v.z = fmaf(dd, w4.z, b4.z);
        v.w = fmaf(dd, w4.w, b4.w);
        __stcs(emb + (base + s) * 32 + lane, v);
    }
    #undef D2ANDBIN
}

extern "C" void kernel_launch(void* const* d_in, const int* in_sizes, int n_in,
                              void* d_out, int out_size)
{
    const float* locs = (const float*)d_in[0];   // [16, 1000, 2]
    const float* xin  = (const float*)d_in[1];   // [16, 1000, 128]
    const float* W    = (const float*)d_in[2];   // [1, 128]
    const float* bias = (const float*)d_in[3];   // [128]
    float* out = (float*)d_out;

    tsp_topk_kernel<<<(BB * NN) / WPB, NTHREADS, 0, 0>>>(locs, xin, W, bias, out);
}